// round 1
// baseline (speedup 1.0000x reference)
#include <cuda_runtime.h>
#include <math.h>

#define Bc    2
#define Tc    2048
#define Ec    2048
#define Hc    16
#define HKVc  4
#define Mc    4
#define HDc   32
#define DVc   128          // Mc*HDc
#define NREPc 4
#define BTc   (Bc*Tc)      // 4096
#define KVE   (Ec/NREPc)   // 512

// ---------------- scratch (device globals; no allocations allowed) ----------
__device__ float g_q[(size_t)BTc * Ec];     // 32 MB : Q proj (B,T,64,32)
__device__ float g_k[(size_t)BTc * KVE];    //  8 MB : K proj (B,T,16,32)
__device__ float g_v[(size_t)BTc * KVE];    //  8 MB : V proj (B,T,4,128)
__device__ float g_comb[(size_t)BTc * Ec];  // 32 MB : combined / normed (B,T,H,128)

// =====================================================================
// SGEMM:  C[MR,N] = A[MR,K] * W[N,K]^T   (both row-major, K contiguous)
// 128x128 tile, BK=8, 256 threads, 8x8 register micro-tile.
// All dims are multiples of 128/8 here -> no bounds checks.
// =====================================================================
__global__ __launch_bounds__(256) void sgemm_nt(
    const float* __restrict__ A, const float* __restrict__ W,
    float* __restrict__ C, int MR, int N, int K)
{
    __shared__ float As[8][128];
    __shared__ float Bs[8][128];
    const int tid  = threadIdx.x;
    const int tx   = tid & 15;          // 0..15
    const int ty   = tid >> 4;          // 0..15
    const int lrow = tid >> 1;          // 0..127
    const int lk   = (tid & 1) * 4;     // 0 or 4

    const float* Ap = A + (size_t)(blockIdx.y * 128 + lrow) * K + lk;
    const float* Wp = W + (size_t)(blockIdx.x * 128 + lrow) * K + lk;

    float acc[8][8];
#pragma unroll
    for (int i = 0; i < 8; i++)
#pragma unroll
        for (int j = 0; j < 8; j++) acc[i][j] = 0.f;

    for (int k0 = 0; k0 < K; k0 += 8) {
        float4 av = *(const float4*)(Ap + k0);
        float4 wv = *(const float4*)(Wp + k0);
        As[lk + 0][lrow] = av.x;  As[lk + 1][lrow] = av.y;
        As[lk + 2][lrow] = av.z;  As[lk + 3][lrow] = av.w;
        Bs[lk + 0][lrow] = wv.x;  Bs[lk + 1][lrow] = wv.y;
        Bs[lk + 2][lrow] = wv.z;  Bs[lk + 3][lrow] = wv.w;
        __syncthreads();
#pragma unroll
        for (int kk = 0; kk < 8; kk++) {
            float a[8], b[8];
            *(float4*)(a)     = *(const float4*)&As[kk][ty * 8];
            *(float4*)(a + 4) = *(const float4*)&As[kk][ty * 8 + 4];
            *(float4*)(b)     = *(const float4*)&Bs[kk][tx * 8];
            *(float4*)(b + 4) = *(const float4*)&Bs[kk][tx * 8 + 4];
#pragma unroll
            for (int i = 0; i < 8; i++)
#pragma unroll
                for (int j = 0; j < 8; j++)
                    acc[i][j] += a[i] * b[j];
        }
        __syncthreads();
    }

#pragma unroll
    for (int i = 0; i < 8; i++) {
        float* Cp = C + (size_t)(blockIdx.y * 128 + ty * 8 + i) * N
                      + blockIdx.x * 128 + tx * 8;
        *(float4*)(Cp)     = make_float4(acc[i][0], acc[i][1], acc[i][2], acc[i][3]);
        *(float4*)(Cp + 4) = make_float4(acc[i][4], acc[i][5], acc[i][6], acc[i][7]);
    }
}

// =====================================================================
// Interleaved RoPE in-place on (BT, nh, 32). One thread per (row,head,pair).
// =====================================================================
__global__ void rope_kernel(float* __restrict__ x,
                            const float* __restrict__ cs,
                            const float* __restrict__ sn, int nh)
{
    int idx = blockIdx.x * 256 + threadIdx.x;
    int total = BTc * nh * (HDc / 2);
    if (idx >= total) return;
    int p    = idx & (HDc / 2 - 1);     // pair 0..15
    int rest = idx >> 4;
    int h    = rest % nh;
    int row  = rest / nh;
    int t    = row & (Tc - 1);
    float c = cs[t * (HDc / 2) + p];
    float s = sn[t * (HDc / 2) + p];
    float* ptr = x + ((size_t)row * nh + h) * HDc + 2 * p;
    float x1 = ptr[0], x2 = ptr[1];
    ptr[0] = x1 * c - x2 * s;
    ptr[1] = x1 * s + x2 * c;
}

// =====================================================================
// Flash attention, one block per (qtile=64 rows, h, m, b).
// D_qk = 32, D_v = 128.  Online softmax, causal.
// Thread layout: g = tid&7 (owns v-dims g,g+8,...,g+120), r2 = tid>>3;
// each thread handles rows r2 and r2+32.
// Result scaled by map_w[m] and atomicAdd'ed into combined (B,T,H,128).
// =====================================================================
#define FBM 64
#define FBN 64
#define FLASH_SMEM ((64*33 + 64*33 + 64*128 + 64*65) * 4)   // 66304 B

__global__ __launch_bounds__(256) void flash_kernel(
    const float* __restrict__ Q, const float* __restrict__ Kb,
    const float* __restrict__ Vb, const float* __restrict__ rawmap,
    const float* __restrict__ wscale, float* __restrict__ Out)
{
    extern __shared__ float smem[];
    float* sQ = smem;                 // [64][33]
    float* sK = sQ + 64 * 33;         // [64][33]
    float* sV = sK + 64 * 33;         // [64][128]
    float* sP = sV + 64 * 128;        // [64][65]

    const int qt  = blockIdx.x;
    const int h   = blockIdx.y >> 2;
    const int m   = blockIdx.y & 3;
    const int b   = blockIdx.z;
    const int hkv = h >> 2;
    const int tid = threadIdx.x;
    const int g   = tid & 7;
    const int r2  = tid >> 3;         // 0..31
    const int q0  = qt * FBM;
    const float scale = 0.17677669529663687f;  // 32^-0.5
    const float mapw  = tanhf(rawmap[m]) * wscale[0];

    // ---- load Q tile (64 rows x 32), coalesced, store padded ----
    {
#pragma unroll
        for (int u = 0; u < 2; u++) {
            int fi  = u * 256 + tid;        // float4 index over 64x8
            int lr  = fi >> 3;
            int c4  = (fi & 7) * 4;
            const float4 v4 = *(const float4*)(Q +
                ((size_t)(b * Tc + q0 + lr) * (Hc * Mc) + (h * Mc + m)) * HDc + c4);
            float* dst = sQ + lr * 33 + c4;
            dst[0] = v4.x; dst[1] = v4.y; dst[2] = v4.z; dst[3] = v4.w;
        }
    }

    float mi[2] = {-1e30f, -1e30f};
    float li[2] = {0.f, 0.f};
    float acc[2][16];
#pragma unroll
    for (int a = 0; a < 2; a++)
#pragma unroll
        for (int j = 0; j < 16; j++) acc[a][j] = 0.f;

    for (int jt = 0; jt <= qt; jt++) {
        const int k0 = jt * FBN;
        __syncthreads();     // previous iteration's sK/sV/sP fully consumed
        // ---- load K tile (64x32) ----
#pragma unroll
        for (int u = 0; u < 2; u++) {
            int fi = u * 256 + tid;
            int lr = fi >> 3;
            int c4 = (fi & 7) * 4;
            const float4 v4 = *(const float4*)(Kb +
                ((size_t)(b * Tc + k0 + lr) * (HKVc * Mc) + (hkv * Mc + m)) * HDc + c4);
            float* dst = sK + lr * 33 + c4;
            dst[0] = v4.x; dst[1] = v4.y; dst[2] = v4.z; dst[3] = v4.w;
        }
        // ---- load V tile (64x128), fully coalesced ----
#pragma unroll
        for (int u = 0; u < 8; u++) {
            int fi = u * 256 + tid;         // float4 index over 64x32
            int lr = fi >> 5;
            int c4 = (fi & 31) * 4;
            *(float4*)(sV + lr * 128 + c4) = *(const float4*)(Vb +
                ((size_t)(b * Tc + k0 + lr) * HKVc + hkv) * DVc + c4);
        }
        __syncthreads();

        const bool diag = (jt == qt);
        // ---- scores + online softmax for this tile ----
#pragma unroll
        for (int half = 0; half < 2; half++) {
            const int ri = r2 + half * 32;
            const int qi = q0 + ri;
            const float* qrow = sQ + ri * 33;
            float sc[8];
#pragma unroll
            for (int cc = 0; cc < 8; cc++) {
                const int c = g * 8 + cc;
                const float* krow = sK + c * 33;
                float d = 0.f;
#pragma unroll
                for (int dd = 0; dd < HDc; dd++) d += qrow[dd] * krow[dd];
                d *= scale;
                if (diag && (k0 + c > qi)) d = -1e30f;
                sc[cc] = d;
            }
            float tmax = sc[0];
#pragma unroll
            for (int cc = 1; cc < 8; cc++) tmax = fmaxf(tmax, sc[cc]);
#pragma unroll
            for (int o = 1; o < 8; o <<= 1)
                tmax = fmaxf(tmax, __shfl_xor_sync(0xffffffffu, tmax, o));
            const float mnew  = fmaxf(mi[half], tmax);
            const float alpha = __expf(mi[half] - mnew);
            float rsum = 0.f;
#pragma unroll
            for (int cc = 0; cc < 8; cc++) {
                float p = __expf(sc[cc] - mnew);
                rsum += p;
                sP[ri * 65 + g * 8 + cc] = p;
            }
#pragma unroll
            for (int o = 1; o < 8; o <<= 1)
                rsum += __shfl_xor_sync(0xffffffffu, rsum, o);
            li[half] = li[half] * alpha + rsum;
            mi[half] = mnew;
#pragma unroll
            for (int j = 0; j < 16; j++) acc[half][j] *= alpha;
        }
        __syncthreads();

        // ---- P @ V ----
#pragma unroll
        for (int half = 0; half < 2; half++) {
            const int ri   = r2 + half * 32;
            const int klim = diag ? (ri + 1) : FBN;
            const float* prow = sP + ri * 65;
            for (int kk = 0; kk < klim; kk++) {
                const float p = prow[kk];
                const float* vrow = sV + kk * 128 + g;
#pragma unroll
                for (int j = 0; j < 16; j++)
                    acc[half][j] += p * vrow[8 * j];
            }
        }
    }

    // ---- epilogue: weighted accumulate into combined ----
#pragma unroll
    for (int half = 0; half < 2; half++) {
        const int qi = q0 + r2 + half * 32;
        const float w = mapw / li[half];
        float* dst = Out + ((size_t)(b * Tc + qi) * Hc + h) * DVc + g;
#pragma unroll
        for (int j = 0; j < 16; j++)
            atomicAdd(dst + 8 * j, acc[half][j] * w);
    }
}

// =====================================================================
// RMSNorm over last dim (128) in-place, gamma broadcast per-dim.
// One block (128 threads) per (b,t,h) row.
// =====================================================================
__global__ void rmsnorm_kernel(float* __restrict__ data,
                               const float* __restrict__ gamma)
{
    const int row = blockIdx.x;
    const int tid = threadIdx.x;
    float v  = data[(size_t)row * 128 + tid];
    float ss = v * v;
#pragma unroll
    for (int o = 16; o; o >>= 1) ss += __shfl_xor_sync(0xffffffffu, ss, o);
    __shared__ float ws[4];
    if ((tid & 31) == 0) ws[tid >> 5] = ss;
    __syncthreads();
    const float tot = ws[0] + ws[1] + ws[2] + ws[3];
    const float r = rsqrtf(tot * (1.f / 128.f) + 1e-5f);
    data[(size_t)row * 128 + tid] = v * r * gamma[tid];
}

// =====================================================================
extern "C" void kernel_launch(void* const* d_in, const int* in_sizes, int n_in,
                              void* d_out, int out_size)
{
    (void)in_sizes; (void)n_in; (void)out_size;
    const float* x      = (const float*)d_in[0];
    const float* cosb   = (const float*)d_in[1];
    const float* sinb   = (const float*)d_in[2];
    const float* q_w    = (const float*)d_in[3];
    const float* k_w    = (const float*)d_in[4];
    const float* v_w    = (const float*)d_in[5];
    const float* out_w  = (const float*)d_in[6];
    const float* rawmap = (const float*)d_in[7];
    const float* wscale = (const float*)d_in[8];
    const float* gamma  = (const float*)d_in[9];

    float *qp, *kp, *vp, *cp;
    cudaGetSymbolAddress((void**)&qp, g_q);
    cudaGetSymbolAddress((void**)&kp, g_k);
    cudaGetSymbolAddress((void**)&vp, g_v);
    cudaGetSymbolAddress((void**)&cp, g_comb);

    cudaFuncSetAttribute(flash_kernel,
                         cudaFuncAttributeMaxDynamicSharedMemorySize, FLASH_SMEM);

    // Projections
    sgemm_nt<<<dim3(Ec / 128,  BTc / 128), 256>>>(x, q_w, qp, BTc, Ec,  Ec);
    sgemm_nt<<<dim3(KVE / 128, BTc / 128), 256>>>(x, k_w, kp, BTc, KVE, Ec);
    sgemm_nt<<<dim3(KVE / 128, BTc / 128), 256>>>(x, v_w, vp, BTc, KVE, Ec);

    // RoPE (Q: 64 heads, K: 16 heads)
    {
        int tq = BTc * (Hc * Mc) * (HDc / 2);
        int tk = BTc * (HKVc * Mc) * (HDc / 2);
        rope_kernel<<<(tq + 255) / 256, 256>>>(qp, cosb, sinb, Hc * Mc);
        rope_kernel<<<(tk + 255) / 256, 256>>>(kp, cosb, sinb, HKVc * Mc);
    }

    // Attention (combined zeroed first; 4 m-slices atomically accumulate)
    cudaMemsetAsync(cp, 0, (size_t)BTc * Ec * sizeof(float));
    flash_kernel<<<dim3(Tc / FBM, Hc * Mc, Bc), 256, FLASH_SMEM>>>(
        qp, kp, vp, rawmap, wscale, cp);

    // RMSNorm (in place) + output projection
    rmsnorm_kernel<<<BTc * Hc, 128>>>(cp, gamma);
    sgemm_nt<<<dim3(Ec / 128, BTc / 128), 256>>>(cp, out_w, (float*)d_out, BTc, Ec, Ec);
}

// round 2
// speedup vs baseline: 11.4257x; 11.4257x over previous
#include <cuda_runtime.h>
#include <math.h>

#define Bc    2
#define Tc    2048
#define Ec    2048
#define Hc    16
#define HKVc  4
#define Mc    4
#define HDc   32
#define DVc   128
#define BTc   (Bc*Tc)      // 4096
#define KVE   512

// ---------------- scratch (device globals; no allocations allowed) ----------
__device__ float g_q[(size_t)BTc * Ec];     // Q proj (B,T,64,32)
__device__ float g_k[(size_t)BTc * KVE];    // K proj (B,T,16,32)
__device__ float g_v[(size_t)BTc * KVE];    // V proj (B,T,4,128)
__device__ float g_comb[(size_t)BTc * Ec];  // normed combined (B,T,H,128)

// =====================================================================
// SGEMM:  C[.,N] = A[.,K] * W[N,K]^T  row-major.  128x128 tile, BK=8,
// 256 threads, 8x8 micro-tile, register-prefetched global loads.
// blockIdx.z selects (W0,C0) or (W1,C1) so two GEMMs share one launch.
// =====================================================================
__global__ __launch_bounds__(256) void sgemm_nt(
    const float* __restrict__ A,
    const float* __restrict__ W0, float* __restrict__ C0,
    const float* __restrict__ W1, float* __restrict__ C1,
    int N, int K)
{
    const float* W = (blockIdx.z == 0) ? W0 : W1;
    float*       C = (blockIdx.z == 0) ? C0 : C1;

    __shared__ float As[8][128];
    __shared__ float Bs[8][128];
    const int tid  = threadIdx.x;
    const int tx   = tid & 15;
    const int ty   = tid >> 4;
    const int lrow = tid >> 1;
    const int lk   = (tid & 1) * 4;

    const float* Ap = A + (size_t)(blockIdx.y * 128 + lrow) * K + lk;
    const float* Wp = W + (size_t)(blockIdx.x * 128 + lrow) * K + lk;

    float acc[8][8];
#pragma unroll
    for (int i = 0; i < 8; i++)
#pragma unroll
        for (int j = 0; j < 8; j++) acc[i][j] = 0.f;

    float4 av = *(const float4*)(Ap);
    float4 wv = *(const float4*)(Wp);

    for (int k0 = 0; k0 < K; k0 += 8) {
        As[lk + 0][lrow] = av.x;  As[lk + 1][lrow] = av.y;
        As[lk + 2][lrow] = av.z;  As[lk + 3][lrow] = av.w;
        Bs[lk + 0][lrow] = wv.x;  Bs[lk + 1][lrow] = wv.y;
        Bs[lk + 2][lrow] = wv.z;  Bs[lk + 3][lrow] = wv.w;
        __syncthreads();
        float4 av2 = av, wv2 = wv;
        if (k0 + 8 < K) {
            av2 = *(const float4*)(Ap + k0 + 8);
            wv2 = *(const float4*)(Wp + k0 + 8);
        }
#pragma unroll
        for (int kk = 0; kk < 8; kk++) {
            float a[8], b[8];
            *(float4*)(a)     = *(const float4*)&As[kk][ty * 8];
            *(float4*)(a + 4) = *(const float4*)&As[kk][ty * 8 + 4];
            *(float4*)(b)     = *(const float4*)&Bs[kk][tx * 8];
            *(float4*)(b + 4) = *(const float4*)&Bs[kk][tx * 8 + 4];
#pragma unroll
            for (int i = 0; i < 8; i++)
#pragma unroll
                for (int j = 0; j < 8; j++)
                    acc[i][j] += a[i] * b[j];
        }
        __syncthreads();
        av = av2; wv = wv2;
    }

#pragma unroll
    for (int i = 0; i < 8; i++) {
        float* Cp = C + (size_t)(blockIdx.y * 128 + ty * 8 + i) * N
                      + blockIdx.x * 128 + tx * 8;
        *(float4*)(Cp)     = make_float4(acc[i][0], acc[i][1], acc[i][2], acc[i][3]);
        *(float4*)(Cp + 4) = make_float4(acc[i][4], acc[i][5], acc[i][6], acc[i][7]);
    }
}

// =====================================================================
// Interleaved RoPE in-place on (BT, nh, 32).
// =====================================================================
__global__ void rope_kernel(float* __restrict__ x,
                            const float* __restrict__ cs,
                            const float* __restrict__ sn, int nh)
{
    int idx = blockIdx.x * 256 + threadIdx.x;
    int total = BTc * nh * (HDc / 2);
    if (idx >= total) return;
    int p    = idx & (HDc / 2 - 1);
    int rest = idx >> 4;
    int h    = rest % nh;
    int row  = rest / nh;
    int t    = row & (Tc - 1);
    float c = cs[t * (HDc / 2) + p];
    float s = sn[t * (HDc / 2) + p];
    float* ptr = x + ((size_t)row * nh + h) * HDc + 2 * p;
    float x1 = ptr[0], x2 = ptr[1];
    ptr[0] = x1 * c - x2 * s;
    ptr[1] = x1 * s + x2 * c;
}

// =====================================================================
// Fused 4-ensemble flash attention + RMSNorm.
// One block per (qtile=64 rows, h, b).  grid (32, 16, 2), 256 threads.
//
// Pass 1: per k-tile, per m: S = Q_m K_m^T (4x4 micro-tile GEMM),
//         online row-max / row-sum-exp stats (per m).
// Pass 2: per k-tile: recompute S_m, build combined
//         P[i][k] = sum_m (w_m / l_m) * exp(S_m - max_m),
//         then one PV GEMM (4x8 micro-tile) into 64x128 accumulator.
// Epilogue: RMSNorm over 128 dims + gamma, direct store (exclusive rows).
//
// Smem: sQ[4][64][33] | X = union( sK[4][64][33], sP[64][66]+sV[64][128] )
//       | stats[2][4][64]
// =====================================================================
#define QS        (64*33)                 // 2112
#define SQ_FLOATS (4*QS)                  // 8448
#define SP_STRIDE 66
#define SP_FLOATS (64*SP_STRIDE)          // 4224
#define SV_FLOATS (64*128)                // 8192
#define X_FLOATS  (SP_FLOATS + SV_FLOATS) // 12416 (>= sK 8448)
#define FL_SMEM   ((SQ_FLOATS + X_FLOATS + 2*4*64) * 4)   // 85504 B

__global__ __launch_bounds__(256, 2) void flash_kernel(
    const float* __restrict__ Q, const float* __restrict__ Kb,
    const float* __restrict__ Vb, const float* __restrict__ rawmap,
    const float* __restrict__ wscale, const float* __restrict__ gamma,
    float* __restrict__ Out)
{
    extern __shared__ float sm[];
    float* sQ   = sm;                       // [4][64][33]
    float* sX   = sm + SQ_FLOATS;           // K tiles OR (sP | sV)
    float* sStM = sX + X_FLOATS;            // [4][64] row max
    float* sStI = sStM + 4 * 64;            // [4][64] w_m / l_m

    const int qt  = gridDim.x - 1 - blockIdx.x;   // long blocks first
    const int h   = blockIdx.y;
    const int b   = blockIdx.z;
    const int hkv = h >> 2;
    const int tid = threadIdx.x;
    const int tx  = tid & 15;
    const int ty  = tid >> 4;
    const int tx4 = tx * 4;
    const int ty4 = ty * 4;
    const int q0  = qt * 64;
    const float scale = 0.17677669529663687f;   // 32^-0.5

    // ---- load Q tiles for all 4 m (once per block) ----
#pragma unroll
    for (int u = 0; u < 8; u++) {
        int fi = u * 256 + tid;
        int m  = fi >> 9;
        int lr = (fi >> 3) & 63;
        int c4 = (fi & 7) * 4;
        float4 v4 = *(const float4*)(Q +
            ((size_t)(b * Tc + q0 + lr) * 64 + (h * 4 + m)) * HDc + c4);
        float* dst = sQ + m * QS + lr * 33 + c4;
        dst[0] = v4.x; dst[1] = v4.y; dst[2] = v4.z; dst[3] = v4.w;
    }

    float mapw[4];
#pragma unroll
    for (int m = 0; m < 4; m++) mapw[m] = tanhf(rawmap[m]) * wscale[0];

    // ================= PASS 1: softmax stats =================
    float RM[4][4], RS[4][4];
#pragma unroll
    for (int m = 0; m < 4; m++)
#pragma unroll
        for (int r = 0; r < 4; r++) { RM[m][r] = -1e30f; RS[m][r] = 0.f; }

    for (int jt = 0; jt <= qt; jt++) {
        const int k0 = jt * 64;
        __syncthreads();
        // load K tiles (4 m) into X
#pragma unroll
        for (int u = 0; u < 8; u++) {
            int fi = u * 256 + tid;
            int m  = fi >> 9;
            int lr = (fi >> 3) & 63;
            int c4 = (fi & 7) * 4;
            float4 v4 = *(const float4*)(Kb +
                ((size_t)(b * Tc + k0 + lr) * 16 + (hkv * 4 + m)) * HDc + c4);
            float* dst = sX + m * QS + lr * 33 + c4;
            dst[0] = v4.x; dst[1] = v4.y; dst[2] = v4.z; dst[3] = v4.w;
        }
        __syncthreads();
        const bool diag = (jt == qt);

        for (int m = 0; m < 4; m++) {
            const float* Qp = sQ + m * QS + ty4 * 33;
            const float* Kp = sX + m * QS + tx4 * 33;
            float S[4][4];
#pragma unroll
            for (int r = 0; r < 4; r++)
#pragma unroll
                for (int c = 0; c < 4; c++) S[r][c] = 0.f;
#pragma unroll 8
            for (int d = 0; d < 32; d++) {
                float a0 = Qp[d], a1 = Qp[33 + d], a2 = Qp[66 + d], a3 = Qp[99 + d];
                float b0 = Kp[d], b1 = Kp[33 + d], b2 = Kp[66 + d], b3 = Kp[99 + d];
                S[0][0] += a0 * b0; S[0][1] += a0 * b1; S[0][2] += a0 * b2; S[0][3] += a0 * b3;
                S[1][0] += a1 * b0; S[1][1] += a1 * b1; S[1][2] += a1 * b2; S[1][3] += a1 * b3;
                S[2][0] += a2 * b0; S[2][1] += a2 * b1; S[2][2] += a2 * b2; S[2][3] += a2 * b3;
                S[3][0] += a3 * b0; S[3][1] += a3 * b1; S[3][2] += a3 * b2; S[3][3] += a3 * b3;
            }
#pragma unroll
            for (int r = 0; r < 4; r++) {
#pragma unroll
                for (int c = 0; c < 4; c++) {
                    float s = S[r][c] * scale;
                    if (diag && (k0 + tx4 + c > q0 + ty4 + r)) s = -1e30f;
                    S[r][c] = s;
                }
                float tm = fmaxf(fmaxf(S[r][0], S[r][1]), fmaxf(S[r][2], S[r][3]));
#pragma unroll
                for (int o = 1; o < 16; o <<= 1)
                    tm = fmaxf(tm, __shfl_xor_sync(0xffffffffu, tm, o));
                float mnew = fmaxf(RM[m][r], tm);
                float corr = __expf(RM[m][r] - mnew);
                float ps = __expf(S[r][0] - mnew) + __expf(S[r][1] - mnew)
                         + __expf(S[r][2] - mnew) + __expf(S[r][3] - mnew);
#pragma unroll
                for (int o = 1; o < 16; o <<= 1)
                    ps += __shfl_xor_sync(0xffffffffu, ps, o);
                RS[m][r] = RS[m][r] * corr + ps;
                RM[m][r] = mnew;
            }
        }
    }

    __syncthreads();
    if (tx == 0) {
#pragma unroll
        for (int m = 0; m < 4; m++)
#pragma unroll
            for (int r = 0; r < 4; r++) {
                sStM[m * 64 + ty4 + r] = RM[m][r];
                sStI[m * 64 + ty4 + r] = mapw[m] / RS[m][r];
            }
    }
    __syncthreads();

    // ================= PASS 2: combined P, then PV =================
    float acc[4][8];
#pragma unroll
    for (int r = 0; r < 4; r++)
#pragma unroll
        for (int c = 0; c < 8; c++) acc[r][c] = 0.f;

    for (int jt = 0; jt <= qt; jt++) {
        const int k0 = jt * 64;
        __syncthreads();      // prev sP/sV fully consumed
        // load K tiles (4 m) into X
#pragma unroll
        for (int u = 0; u < 8; u++) {
            int fi = u * 256 + tid;
            int m  = fi >> 9;
            int lr = (fi >> 3) & 63;
            int c4 = (fi & 7) * 4;
            float4 v4 = *(const float4*)(Kb +
                ((size_t)(b * Tc + k0 + lr) * 16 + (hkv * 4 + m)) * HDc + c4);
            float* dst = sX + m * QS + lr * 33 + c4;
            dst[0] = v4.x; dst[1] = v4.y; dst[2] = v4.z; dst[3] = v4.w;
        }
        __syncthreads();
        const bool diag = (jt == qt);

        float P[4][4];
#pragma unroll
        for (int r = 0; r < 4; r++)
#pragma unroll
            for (int c = 0; c < 4; c++) P[r][c] = 0.f;

        for (int m = 0; m < 4; m++) {
            const float* Qp = sQ + m * QS + ty4 * 33;
            const float* Kp = sX + m * QS + tx4 * 33;
            float S[4][4];
#pragma unroll
            for (int r = 0; r < 4; r++)
#pragma unroll
                for (int c = 0; c < 4; c++) S[r][c] = 0.f;
#pragma unroll 8
            for (int d = 0; d < 32; d++) {
                float a0 = Qp[d], a1 = Qp[33 + d], a2 = Qp[66 + d], a3 = Qp[99 + d];
                float b0 = Kp[d], b1 = Kp[33 + d], b2 = Kp[66 + d], b3 = Kp[99 + d];
                S[0][0] += a0 * b0; S[0][1] += a0 * b1; S[0][2] += a0 * b2; S[0][3] += a0 * b3;
                S[1][0] += a1 * b0; S[1][1] += a1 * b1; S[1][2] += a1 * b2; S[1][3] += a1 * b3;
                S[2][0] += a2 * b0; S[2][1] += a2 * b1; S[2][2] += a2 * b2; S[2][3] += a2 * b3;
                S[3][0] += a3 * b0; S[3][1] += a3 * b1; S[3][2] += a3 * b2; S[3][3] += a3 * b3;
            }
#pragma unroll
            for (int r = 0; r < 4; r++) {
                float sm_ = sStM[m * 64 + ty4 + r];
                float si  = sStI[m * 64 + ty4 + r];
#pragma unroll
                for (int c = 0; c < 4; c++) {
                    float s = S[r][c] * scale;
                    if (diag && (k0 + tx4 + c > q0 + ty4 + r)) s = -1e30f;
                    P[r][c] += si * __expf(s - sm_);
                }
            }
        }
        __syncthreads();      // K consumed; X becomes sP|sV

        // write combined P (row-major [64][66]) and load V tile
#pragma unroll
        for (int r = 0; r < 4; r++)
#pragma unroll
            for (int c = 0; c < 4; c++)
                sX[(ty4 + r) * SP_STRIDE + tx4 + c] = P[r][c];
#pragma unroll
        for (int u = 0; u < 8; u++) {
            int fi = u * 256 + tid;
            int lr = fi >> 5;
            int c4 = (fi & 31) * 4;
            *(float4*)(sX + SP_FLOATS + lr * 128 + c4) = *(const float4*)(Vb +
                ((size_t)(b * Tc + k0 + lr) * HKVc + hkv) * DVc + c4);
        }
        __syncthreads();

        // PV: acc[4][8] over kk; thread owns cols {tx4..tx4+3, 64+tx4..+3}
        const float* Pp = sX + ty4 * SP_STRIDE;
        const float* Vp = sX + SP_FLOATS;
#pragma unroll 8
        for (int kk = 0; kk < 64; kk++) {
            float a0 = Pp[kk], a1 = Pp[SP_STRIDE + kk],
                  a2 = Pp[2 * SP_STRIDE + kk], a3 = Pp[3 * SP_STRIDE + kk];
            float4 bl = *(const float4*)(Vp + kk * 128 + tx4);
            float4 bh = *(const float4*)(Vp + kk * 128 + 64 + tx4);
            acc[0][0] += a0 * bl.x; acc[0][1] += a0 * bl.y; acc[0][2] += a0 * bl.z; acc[0][3] += a0 * bl.w;
            acc[0][4] += a0 * bh.x; acc[0][5] += a0 * bh.y; acc[0][6] += a0 * bh.z; acc[0][7] += a0 * bh.w;
            acc[1][0] += a1 * bl.x; acc[1][1] += a1 * bl.y; acc[1][2] += a1 * bl.z; acc[1][3] += a1 * bl.w;
            acc[1][4] += a1 * bh.x; acc[1][5] += a1 * bh.y; acc[1][6] += a1 * bh.z; acc[1][7] += a1 * bh.w;
            acc[2][0] += a2 * bl.x; acc[2][1] += a2 * bl.y; acc[2][2] += a2 * bl.z; acc[2][3] += a2 * bl.w;
            acc[2][4] += a2 * bh.x; acc[2][5] += a2 * bh.y; acc[2][6] += a2 * bh.z; acc[2][7] += a2 * bh.w;
            acc[3][0] += a3 * bl.x; acc[3][1] += a3 * bl.y; acc[3][2] += a3 * bl.z; acc[3][3] += a3 * bl.w;
            acc[3][4] += a3 * bh.x; acc[3][5] += a3 * bh.y; acc[3][6] += a3 * bh.z; acc[3][7] += a3 * bh.w;
        }
    }

    // ---- epilogue: fused RMSNorm + gamma + store ----
    float4 g0 = *(const float4*)(gamma + tx4);
    float4 g1 = *(const float4*)(gamma + 64 + tx4);
#pragma unroll
    for (int r = 0; r < 4; r++) {
        float ss = 0.f;
#pragma unroll
        for (int c = 0; c < 8; c++) ss += acc[r][c] * acc[r][c];
#pragma unroll
        for (int o = 1; o < 16; o <<= 1)
            ss += __shfl_xor_sync(0xffffffffu, ss, o);
        float rs = rsqrtf(ss * (1.f / 128.f) + 1e-5f);
        float* dst = Out + ((size_t)(b * Tc + q0 + ty4 + r) * Hc + h) * DVc;
        *(float4*)(dst + tx4) = make_float4(
            acc[r][0] * rs * g0.x, acc[r][1] * rs * g0.y,
            acc[r][2] * rs * g0.z, acc[r][3] * rs * g0.w);
        *(float4*)(dst + 64 + tx4) = make_float4(
            acc[r][4] * rs * g1.x, acc[r][5] * rs * g1.y,
            acc[r][6] * rs * g1.z, acc[r][7] * rs * g1.w);
    }
}

// =====================================================================
extern "C" void kernel_launch(void* const* d_in, const int* in_sizes, int n_in,
                              void* d_out, int out_size)
{
    (void)in_sizes; (void)n_in; (void)out_size;
    const float* x      = (const float*)d_in[0];
    const float* cosb   = (const float*)d_in[1];
    const float* sinb   = (const float*)d_in[2];
    const float* q_w    = (const float*)d_in[3];
    const float* k_w    = (const float*)d_in[4];
    const float* v_w    = (const float*)d_in[5];
    const float* out_w  = (const float*)d_in[6];
    const float* rawmap = (const float*)d_in[7];
    const float* wscale = (const float*)d_in[8];
    const float* gamma  = (const float*)d_in[9];

    float *qp, *kp, *vp, *cp;
    cudaGetSymbolAddress((void**)&qp, g_q);
    cudaGetSymbolAddress((void**)&kp, g_k);
    cudaGetSymbolAddress((void**)&vp, g_v);
    cudaGetSymbolAddress((void**)&cp, g_comb);

    cudaFuncSetAttribute(flash_kernel,
                         cudaFuncAttributeMaxDynamicSharedMemorySize, FL_SMEM);

    // Q projection
    sgemm_nt<<<dim3(Ec / 128, BTc / 128, 1), 256>>>(x, q_w, qp, q_w, qp, Ec, Ec);
    // K and V projections in one launch (z selects weight/output)
    sgemm_nt<<<dim3(KVE / 128, BTc / 128, 2), 256>>>(x, k_w, kp, v_w, vp, KVE, Ec);

    // RoPE (Q: 64 heads, K: 16 heads)
    {
        int tq = BTc * (Hc * Mc) * (HDc / 2);
        int tk = BTc * (HKVc * Mc) * (HDc / 2);
        rope_kernel<<<(tq + 255) / 256, 256>>>(qp, cosb, sinb, Hc * Mc);
        rope_kernel<<<(tk + 255) / 256, 256>>>(kp, cosb, sinb, HKVc * Mc);
    }

    // Fused 4-ensemble flash attention + RMSNorm
    flash_kernel<<<dim3(Tc / 64, Hc, Bc), 256, FL_SMEM>>>(
        qp, kp, vp, rawmap, wscale, gamma, cp);

    // Output projection
    sgemm_nt<<<dim3(Ec / 128, BTc / 128, 1), 256>>>(cp, out_w, (float*)d_out,
                                                    out_w, (float*)d_out, Ec, Ec);
}